// round 7
// baseline (speedup 1.0000x reference)
#include <cuda_runtime.h>
#include <cuda_fp16.h>
#include <cstdint>

#define NEGC (-10000000.0f)

// ---------------- device globals (pre-converted weights, fp16) ----------------
__device__ __half g_W1h[512 * 256];   // W1T[n][k] = h(W1[k][n])
__device__ __half g_W2h[1024 * 128];  // fp16 copy of W2

// ---------------- helpers ----------------
__device__ __forceinline__ uint32_t smem_u32(const void* p) {
    uint32_t a;
    asm("{ .reg .u64 t; cvta.to.shared.u64 t, %1; cvt.u32.u64 %0, t; }" : "=r"(a) : "l"(p));
    return a;
}
__device__ __forceinline__ uint32_t h2_u32(__half2 h) { return *(uint32_t*)&h; }

__device__ __forceinline__ void ldsm4(uint32_t* r, uint32_t addr) {
    asm volatile("ldmatrix.sync.aligned.m8n8.x4.shared.b16 {%0,%1,%2,%3}, [%4];"
        : "=r"(r[0]), "=r"(r[1]), "=r"(r[2]), "=r"(r[3]) : "r"(addr));
}
// f16-accumulate MMA
__device__ __forceinline__ void mmah(uint32_t* d, const uint32_t* a, const uint32_t* b) {
    asm volatile("mma.sync.aligned.m16n8k16.row.col.f16.f16.f16.f16 "
        "{%0,%1}, {%2,%3,%4,%5}, {%6,%7}, {%0,%1};"
        : "+r"(d[0]), "+r"(d[1])
        : "r"(a[0]), "r"(a[1]), "r"(a[2]), "r"(a[3]), "r"(b[0]), "r"(b[1]));
}

// ---------------- smem layout (bytes) ----------------
#define OFF_A     0u        // 65536 : A [128 m x 256 k] f16, swizzled
#define OFF_A2    65536u    // 8192  : A2 [16 x 256] f16 (rows 0,1 = obs_x)
#define OFF_B     73728u    // 49152 : B triple buffer (3 x [128 n x 64 k] f16); Z blk3 overlays 0..32K
#define OFF_Z012  122880u   // 98304 : Z blocks 0..2 ([128 r x 128 c] f16 each)
#define OFF_XSF   221184u   // 2048  : x f16 [2][512]
#define OFF_BS1   223232u   // 1024  : b1 f16
#define OFF_BS2   224256u   // 256   : b2 f16
#define SMEM_TOTAL 224512u
// scratch overlay on OFF_A after GEMM:
#define SC_RED   0u
#define SC_BET   2048u
#define SC_C     2560u
#define SC_PART  6656u
#define SC_MSC   14848u

// Z address: row r, global col-pair p (cols 2p,2p+1). Pass-major blocks of 64 pairs.
__device__ __forceinline__ uint32_t zaddr(int r, int p) {
    int blk = p >> 6, pl = p & 63;
    uint32_t base = (blk < 3) ? (OFF_Z012 + (uint32_t)blk * 32768u) : OFF_B;
    return base + (uint32_t)r * 256u + ((uint32_t)(pl ^ (r & 63)) << 2);
}

// ---------------- prep: convert weights to fp16 ----------------
__global__ void prep_kernel(const float* __restrict__ W1, const float* __restrict__ W2) {
    int i = blockIdx.x * blockDim.x + threadIdx.x;
    int stride = gridDim.x * blockDim.x;
    for (int idx = i; idx < 512 * 256; idx += stride) {
        int n = idx & 511, k = idx >> 9;
        g_W1h[n * 256 + k] = __float2half(W1[k * 512 + n]);
    }
    for (int idx = i; idx < 1024 * 128; idx += stride)
        g_W2h[idx] = __float2half(W2[idx]);
}

// issue cp.async for W1 chunk ci into buffer ci%3
__device__ __forceinline__ void load_chunk(uint32_t sb, int ci, int t) {
    uint32_t dst = sb + OFF_B + (uint32_t)(ci % 3) * 16384u;
    const __half* src = g_W1h + (size_t)((ci >> 2) * 128) * 256 + (ci & 3) * 64;
    #pragma unroll
    for (int i = 0; i < 2; i++) {
        int idx = i * 512 + t;
        int n = idx >> 3, u = idx & 7;
        int up = u ^ (n & 7);
        uint32_t d = dst + (uint32_t)n * 128u + (uint32_t)up * 16u;
        const void* s = src + (size_t)n * 256 + u * 8;
        asm volatile("cp.async.cg.shared.global [%0], [%1], 16;" :: "r"(d), "l"(s));
    }
    asm volatile("cp.async.commit_group;" ::: "memory");
}

// ---------------- main fused kernel: 2 batches per CTA ----------------
__global__ __launch_bounds__(512, 1)
void agent_main(const float* __restrict__ obs_x,
                const float* __restrict__ others,
                const int*   __restrict__ action_mask,
                const float* __restrict__ b1g,
                const float* __restrict__ b2g,
                float*       __restrict__ out)
{
    extern __shared__ char sm[];
    const uint32_t sb = smem_u32(sm);
    const int t = threadIdx.x, w = t >> 5, lane = t & 31;
    const int b0 = blockIdx.x * 2;

    __half* bs1h = (__half*)(sm + OFF_BS1);
    __half* bs2h = (__half*)(sm + OFF_BS2);
    __half* xsfh = (__half*)(sm + OFF_XSF);

    bs1h[t] = __float2half(b1g[t]);
    if (t < 128) bs2h[t] = __float2half(b2g[t]);

    // kick off W1 chunks 0 and 1 ASAP (3-stage ring)
    load_chunk(sb, 0, t);
    load_chunk(sb, 1, t);

    // ---- A: others (2 batches) fp32 -> f16, XOR-swizzled 16B units ----
    #pragma unroll
    for (int it = 0; it < 8; it++) {
        int idx = it * 512 + t;
        int row = idx >> 5, u = idx & 31;
        int up = (u & 24) | ((u ^ row) & 7);
        const float* src = others + (size_t)(b0 + (row >> 6)) * 16384 + (row & 63) * 256 + u * 8;
        float4 v0 = *(const float4*)src;
        float4 v1 = *(const float4*)(src + 4);
        uint4 pk = make_uint4(h2_u32(__floats2half2_rn(v0.x, v0.y)),
                              h2_u32(__floats2half2_rn(v0.z, v0.w)),
                              h2_u32(__floats2half2_rn(v1.x, v1.y)),
                              h2_u32(__floats2half2_rn(v1.z, v1.w)));
        *(uint4*)(sm + OFF_A + row * 512 + up * 16) = pk;
    }
    // ---- A2: rows 0,1 = obs_x, rows 2..15 = 0 ----
    {
        int row = t >> 5, u = t & 31;
        int up = (u & 24) | ((u ^ row) & 7);
        uint4 pk = make_uint4(0u, 0u, 0u, 0u);
        if (row < 2) {
            const float* src = obs_x + (size_t)(b0 + row) * 256 + u * 8;
            float4 v0 = *(const float4*)src;
            float4 v1 = *(const float4*)(src + 4);
            pk = make_uint4(h2_u32(__floats2half2_rn(v0.x, v0.y)),
                            h2_u32(__floats2half2_rn(v0.z, v0.w)),
                            h2_u32(__floats2half2_rn(v1.x, v1.y)),
                            h2_u32(__floats2half2_rn(v1.z, v1.w)));
        }
        *(uint4*)(sm + OFF_A2 + row * 512 + up * 16) = pk;
    }

    // ---- warp tiling: 4 m-slabs (32 rows) x 4 n-quarters (32 cols per 128-col pass) ----
    const int wm = w & 3, wn = w >> 2;
    const bool is_obs = (wm == wn);   // warps 0,5,10,15: one per SMSP, distinct wn
    const int m0 = wm * 32;
    const int lrow = lane & 15, lkh = lane >> 4;
    const int arow0 = m0 + lrow, arow1 = m0 + 16 + lrow;
    const uint32_t a_base0 = sb + OFF_A + (uint32_t)arow0 * 512u;
    const uint32_t a_base1 = sb + OFF_A + (uint32_t)arow1 * 512u;
    const uint32_t a2_base = sb + OFF_A2 + (uint32_t)lrow * 512u;
    const int g = lane >> 2, c = lane & 3;

    uint32_t acc[2][4][2];
    uint32_t oacc[4][2];

    for (int ci = 0; ci < 16; ci++) {
        const int pass = ci >> 2, kc = ci & 3;
        if (ci == 15) asm volatile("cp.async.wait_group 0;" ::: "memory");
        else          asm volatile("cp.async.wait_group 1;" ::: "memory");
        __syncthreads();
        if (ci <= 13) load_chunk(sb, ci + 2, t);

        if (kc == 0) {
            #pragma unroll
            for (int mi = 0; mi < 2; mi++)
                #pragma unroll
                for (int ni = 0; ni < 4; ni++) { acc[mi][ni][0] = 0u; acc[mi][ni][1] = 0u; }
            #pragma unroll
            for (int q = 0; q < 4; q++) { oacc[q][0] = 0u; oacc[q][1] = 0u; }
        }

        const uint32_t bbuf = sb + OFF_B + (uint32_t)(ci % 3) * 16384u;
        #pragma unroll
        for (int ks = 0; ks < 4; ks++) {
            const int u = kc * 8 + ks * 2 + lkh;
            uint32_t af0[4], af1[4];
            ldsm4(af0, a_base0 + (uint32_t)(((u & 24) | ((u ^ arow0) & 7)) << 4));
            ldsm4(af1, a_base1 + (uint32_t)(((u & 24) | ((u ^ arow1) & 7)) << 4));
            uint32_t bf0[4], bf1[4];
            const int n0 = wn * 32 + lrow, n1 = n0 + 16;
            ldsm4(bf0, bbuf + (uint32_t)n0 * 128u + (uint32_t)(((ks * 2 + lkh) ^ (n0 & 7)) << 4));
            ldsm4(bf1, bbuf + (uint32_t)n1 * 128u + (uint32_t)(((ks * 2 + lkh) ^ (n1 & 7)) << 4));

            mmah(acc[0][0], af0, bf0);      mmah(acc[0][1], af0, bf0 + 2);
            mmah(acc[0][2], af0, bf1);      mmah(acc[0][3], af0, bf1 + 2);
            mmah(acc[1][0], af1, bf0);      mmah(acc[1][1], af1, bf0 + 2);
            mmah(acc[1][2], af1, bf1);      mmah(acc[1][3], af1, bf1 + 2);

            if (is_obs) {  // obs projection: 4 warps cover all 128 cols, B frags reused
                uint32_t a2f[4];
                ldsm4(a2f, a2_base + (uint32_t)(((u & 24) | ((u ^ lrow) & 7)) << 4));
                mmah(oacc[0], a2f, bf0);
                mmah(oacc[1], a2f, bf0 + 2);
                mmah(oacc[2], a2f, bf1);
                mmah(oacc[3], a2f, bf1 + 2);
            }
        }

        if (kc == 3) {
            if (pass == 3) __syncthreads();  // B ring dies; Z block3 overlays buffers 0,1
            #pragma unroll
            for (int mi = 0; mi < 2; mi++)
                #pragma unroll
                for (int ni = 0; ni < 4; ni++) {
                    const int ncol = pass * 128 + wn * 32 + ni * 8 + 2 * c;
                    const __half2 bias = *(__half2*)(sm + OFF_BS1 + ncol * 2);
                    const int p = ncol >> 1;
                    const int r0 = m0 + mi * 16 + g;
                    *(__half2*)(sm + zaddr(r0, p)) =
                        __hadd2(*(__half2*)&acc[mi][ni][0], bias);
                    *(__half2*)(sm + zaddr(r0 + 8, p)) =
                        __hadd2(*(__half2*)&acc[mi][ni][1], bias);
                }
            if (is_obs && g < 2) {  // obs rows -> xsf (g = batch)
                #pragma unroll
                for (int q = 0; q < 4; q++) {
                    const int col = pass * 128 + wn * 32 + q * 8 + 2 * c;
                    const __half2 bias = *(__half2*)(sm + OFF_BS1 + col * 2);
                    *(__half2*)(sm + OFF_XSF + (g * 512 + col) * 2) =
                        __hadd2(*(__half2*)&oacc[q][0], bias);
                }
            }
        }
    }
    __syncthreads();   // GEMM done; A region becomes scratch

    float* redp = (float*)(sm + SC_RED);
    float* betp = (float*)(sm + SC_BET);
    float* carr = (float*)(sm + SC_C);
    float* mscp = (float*)(sm + SC_MSC);

    // ---- alpha[n] = x . y[n] / sqrt(512) ----
    {
        int batch = t >> 8, tt = t & 255;
        int n = tt & 63, q = tt >> 6;
        int row = batch * 64 + n;
        const __half* xh = xsfh + batch * 512;
        float s = 0.f;
        #pragma unroll 8
        for (int pp = 0; pp < 64; pp++) {
            int p = q * 64 + pp;
            float2 yf = __half22float2(*(__half2*)(sm + zaddr(row, p)));
            float2 xf = __half22float2(*(const __half2*)(xh + 2 * p));
            s = fmaf(xf.x, yf.x, s);
            s = fmaf(xf.y, yf.y, s);
        }
        redp[t] = s;
    }
    __syncthreads();
    if (t < 128) {
        int batch = t >> 6, n = t & 63;
        const float* r = redp + batch * 256;
        betp[t] = (r[n] + r[64 + n] + r[128 + n] + r[192 + n]) * 0.04419417382415922f;
    }
    __syncthreads();
    if (w < 2) {  // softmax over 64
        float a0 = betp[w * 64 + lane], a1 = betp[w * 64 + 32 + lane];
        float m = fmaxf(a0, a1);
        #pragma unroll
        for (int off = 16; off; off >>= 1) m = fmaxf(m, __shfl_xor_sync(~0u, m, off));
        float e0 = __expf(a0 - m), e1 = __expf(a1 - m);
        float s = e0 + e1;
        #pragma unroll
        for (int off = 16; off; off >>= 1) s += __shfl_xor_sync(~0u, s, off);
        float inv = 1.0f / s;
        betp[w * 64 + lane] = e0 * inv;
        betp[w * 64 + 32 + lane] = e1 * inv;
    }
    __syncthreads();

    // ---- c[d] = sum_n beta[n] * y[n][d] ----
    {
        int batch = t >> 8, p = t & 255;
        float c0 = 0.f, c1 = 0.f;
        #pragma unroll 8
        for (int n = 0; n < 64; n++) {
            float be = betp[batch * 64 + n];
            float2 yf = __half22float2(*(__half2*)(sm + zaddr(batch * 64 + n, p)));
            c0 = fmaf(be, yf.x, c0);
            c1 = fmaf(be, yf.y, c1);
        }
        carr[batch * 512 + 2 * p]     = c0;
        carr[batch * 512 + 2 * p + 1] = c1;
    }
    __syncthreads();

    // ---- o2 = [x, c] @ W2 + b2: W2 read once, both batches ----
    {
        int q = t >> 6;      // k-chunk 0..7 of 128; q<4 -> x (f16), else c (f32)
        int jp = t & 63;
        const __half* w2p = g_W2h + (size_t)(q * 128) * 128 + jp * 2;
        float a00 = 0.f, a01 = 0.f, a10 = 0.f, a11 = 0.f;
        if (q < 4) {
            const __half* x0 = xsfh + q * 128;
            const __half* x1 = x0 + 512;
            #pragma unroll 8
            for (int k = 0; k < 128; k++) {
                float2 hf = __half22float2(*(const __half2*)(w2p + (size_t)k * 128));
                float v0 = __half2float(x0[k]), v1 = __half2float(x1[k]);
                a00 = fmaf(v0, hf.x, a00); a01 = fmaf(v0, hf.y, a01);
                a10 = fmaf(v1, hf.x, a10); a11 = fmaf(v1, hf.y, a11);
            }
        } else {
            const float* c0p = carr + (q - 4) * 128;
            const float* c1p = c0p + 512;
            #pragma unroll 8
            for (int k = 0; k < 128; k++) {
                float2 hf = __half22float2(*(const __half2*)(w2p + (size_t)k * 128));
                float v0 = c0p[k], v1 = c1p[k];
                a00 = fmaf(v0, hf.x, a00); a01 = fmaf(v0, hf.y, a01);
                a10 = fmaf(v1, hf.x, a10); a11 = fmaf(v1, hf.y, a11);
            }
        }
        float2* p2 = (float2*)(sm + SC_PART);
        p2[q * 64 + jp]       = make_float2(a00, a01);
        p2[512 + q * 64 + jp] = make_float2(a10, a11);
    }
    __syncthreads();

    // ---- combine + softmax over 128 + mask + write ----
    float sval = 0.f, eval = 0.f;
    int batch = 0, j = 0;
    if (t < 256) {
        batch = t >> 7; j = t & 127;
        const float2* p2 = (const float2*)(sm + SC_PART) + batch * 512 + (j >> 1);
        float s = 0.f;
        #pragma unroll
        for (int q = 0; q < 8; q++) {
            float2 v = p2[q * 64];
            s += (j & 1) ? v.y : v.x;
        }
        sval = s + __half2float(bs2h[j]);
        float m = sval;
        #pragma unroll
        for (int off = 16; off; off >>= 1) m = fmaxf(m, __shfl_xor_sync(~0u, m, off));
        if (lane == 0) mscp[w] = m;
    }
    __syncthreads();
    if (t < 256) {
        float m = fmaxf(fmaxf(mscp[batch * 4 + 0], mscp[batch * 4 + 1]),
                        fmaxf(mscp[batch * 4 + 2], mscp[batch * 4 + 3]));
        eval = __expf(sval - m);
        float ss = eval;
        #pragma unroll
        for (int off = 16; off; off >>= 1) ss += __shfl_xor_sync(~0u, ss, off);
        if (lane == 0) mscp[8 + w] = ss;
    }
    __syncthreads();
    if (t < 256) {
        float ssum = mscp[8 + batch * 4] + mscp[8 + batch * 4 + 1]
                   + mscp[8 + batch * 4 + 2] + mscp[8 + batch * 4 + 3];
        float soft = eval / ssum;
        float mv = (float)action_mask[(size_t)(b0 + batch) * 128 + j];
        out[(size_t)(b0 + batch) * 128 + j] = soft + NEGC * (1.0f - mv);
    }
}

extern "C" void kernel_launch(void* const* d_in, const int* in_sizes, int n_in,
                              void* d_out, int out_size)
{
    const float* obs_x       = (const float*)d_in[0];
    const float* others      = (const float*)d_in[1];
    const int*   action_mask = (const int*)  d_in[2];
    const float* W1          = (const float*)d_in[3];
    const float* b1          = (const float*)d_in[4];
    const float* W2          = (const float*)d_in[5];
    const float* b2          = (const float*)d_in[6];
    // d_in[7..10] = W3,b3,W4,b4: dead in reference forward(), unused.

    prep_kernel<<<256, 256>>>(W1, W2);

    cudaFuncSetAttribute(agent_main,
                         cudaFuncAttributeMaxDynamicSharedMemorySize, (int)SMEM_TOTAL);
    agent_main<<<2048, 512, SMEM_TOTAL>>>(obs_x, others, action_mask,
                                          b1, b2, (float*)d_out);
}

// round 8
// speedup vs baseline: 1.0380x; 1.0380x over previous
#include <cuda_runtime.h>
#include <cuda_fp16.h>
#include <cstdint>

#define NEGC (-10000000.0f)

// ---------------- device globals (pre-converted weights, fp16) ----------------
__device__ __half g_W1h[512 * 256];   // W1T[n][k] = h(W1[k][n])
__device__ __half g_W2h[1024 * 128];  // fp16 copy of W2

// ---------------- helpers ----------------
__device__ __forceinline__ uint32_t smem_u32(const void* p) {
    uint32_t a;
    asm("{ .reg .u64 t; cvta.to.shared.u64 t, %1; cvt.u32.u64 %0, t; }" : "=r"(a) : "l"(p));
    return a;
}
__device__ __forceinline__ uint32_t h2_u32(__half2 h) { return *(uint32_t*)&h; }

__device__ __forceinline__ void ldsm4(uint32_t* r, uint32_t addr) {
    asm volatile("ldmatrix.sync.aligned.m8n8.x4.shared.b16 {%0,%1,%2,%3}, [%4];"
        : "=r"(r[0]), "=r"(r[1]), "=r"(r[2]), "=r"(r[3]) : "r"(addr));
}
// f16-accumulate MMA
__device__ __forceinline__ void mmah(uint32_t* d, const uint32_t* a, const uint32_t* b) {
    asm volatile("mma.sync.aligned.m16n8k16.row.col.f16.f16.f16.f16 "
        "{%0,%1}, {%2,%3,%4,%5}, {%6,%7}, {%0,%1};"
        : "+r"(d[0]), "+r"(d[1])
        : "r"(a[0]), "r"(a[1]), "r"(a[2]), "r"(a[3]), "r"(b[0]), "r"(b[1]));
}

// ---------------- smem layout (bytes) ----------------
#define OFF_A     0u        // 65536 : A [128 m x 256 k] f16, swizzled
#define OFF_A2    65536u    // 8192  : A2 [16 x 256] f16 (rows 0,1 = obs_x)
#define OFF_B     73728u    // 49152 : B triple buffer (3 x [128 n x 64 k] f16); Z blk3 overlays 0..32K
#define OFF_Z012  122880u   // 98304 : Z blocks 0..2 ([128 r x 128 c] f16 each)
#define OFF_XSF   221184u   // 2048  : x f16 [2][512]
#define OFF_BS1   223232u   // 1024  : b1 f16
#define OFF_BS2   224256u   // 256   : b2 f16
#define SMEM_TOTAL 224512u
// scratch overlay on OFF_A after GEMM:
#define SC_RED   0u
#define SC_BET   2048u
#define SC_C     2560u
#define SC_PART  6656u
#define SC_MSC   14848u

// Z address: row r, global col-pair p (cols 2p,2p+1). Pass-major blocks of 64 pairs.
__device__ __forceinline__ uint32_t zaddr(int r, int p) {
    int blk = p >> 6, pl = p & 63;
    uint32_t base = (blk < 3) ? (OFF_Z012 + (uint32_t)blk * 32768u) : OFF_B;
    return base + (uint32_t)r * 256u + ((uint32_t)(pl ^ (r & 63)) << 2);
}

// ---------------- prep: convert weights to fp16 ----------------
__global__ void prep_kernel(const float* __restrict__ W1, const float* __restrict__ W2) {
    int i = blockIdx.x * blockDim.x + threadIdx.x;
    int stride = gridDim.x * blockDim.x;
    for (int idx = i; idx < 512 * 256; idx += stride) {
        int n = idx & 511, k = idx >> 9;
        g_W1h[n * 256 + k] = __float2half(W1[k * 512 + n]);
    }
    for (int idx = i; idx < 1024 * 128; idx += stride)
        g_W2h[idx] = __float2half(W2[idx]);
}

// chunk ci -> (half = ci>>3, kc = (ci>>1)&3, pp = ci&1), pass = half*2 + pp
// B chunk = W1T rows [pass*128, +128), k cols [kc*64, +64), into ring buffer ci%3
__device__ __forceinline__ void load_chunk(uint32_t sb, int ci, int t) {
    uint32_t dst = sb + OFF_B + (uint32_t)(ci % 3) * 16384u;
    const int pass = ((ci >> 3) << 1) | (ci & 1);
    const int kc = (ci >> 1) & 3;
    const __half* src = g_W1h + (size_t)(pass * 128) * 256 + kc * 64;
    #pragma unroll
    for (int i = 0; i < 2; i++) {
        int idx = i * 512 + t;
        int n = idx >> 3, u = idx & 7;
        int up = u ^ (n & 7);
        uint32_t d = dst + (uint32_t)n * 128u + (uint32_t)up * 16u;
        const void* s = src + (size_t)n * 256 + u * 8;
        asm volatile("cp.async.cg.shared.global [%0], [%1], 16;" :: "r"(d), "l"(s));
    }
    asm volatile("cp.async.commit_group;" ::: "memory");
}

// ---------------- main fused kernel: 2 batches per CTA ----------------
__global__ __launch_bounds__(512, 1)
void agent_main(const float* __restrict__ obs_x,
                const float* __restrict__ others,
                const int*   __restrict__ action_mask,
                const float* __restrict__ b1g,
                const float* __restrict__ b2g,
                float*       __restrict__ out)
{
    extern __shared__ char sm[];
    const uint32_t sb = smem_u32(sm);
    const int t = threadIdx.x, w = t >> 5, lane = t & 31;
    const int b0 = blockIdx.x * 2;

    __half* bs1h = (__half*)(sm + OFF_BS1);
    __half* bs2h = (__half*)(sm + OFF_BS2);
    __half* xsfh = (__half*)(sm + OFF_XSF);

    bs1h[t] = __float2half(b1g[t]);
    if (t < 128) bs2h[t] = __float2half(b2g[t]);

    // kick off W1 chunks 0 and 1 ASAP (3-stage ring)
    load_chunk(sb, 0, t);
    load_chunk(sb, 1, t);

    // ---- A: others (2 batches) fp32 -> f16, XOR-swizzled 16B units ----
    #pragma unroll
    for (int it = 0; it < 8; it++) {
        int idx = it * 512 + t;
        int row = idx >> 5, u = idx & 31;
        int up = (u & 24) | ((u ^ row) & 7);
        const float* src = others + (size_t)(b0 + (row >> 6)) * 16384 + (row & 63) * 256 + u * 8;
        float4 v0 = *(const float4*)src;
        float4 v1 = *(const float4*)(src + 4);
        uint4 pk = make_uint4(h2_u32(__floats2half2_rn(v0.x, v0.y)),
                              h2_u32(__floats2half2_rn(v0.z, v0.w)),
                              h2_u32(__floats2half2_rn(v1.x, v1.y)),
                              h2_u32(__floats2half2_rn(v1.z, v1.w)));
        *(uint4*)(sm + OFF_A + row * 512 + up * 16) = pk;
    }
    // ---- A2: rows 0,1 = obs_x, rows 2..15 = 0 ----
    {
        int row = t >> 5, u = t & 31;
        int up = (u & 24) | ((u ^ row) & 7);
        uint4 pk = make_uint4(0u, 0u, 0u, 0u);
        if (row < 2) {
            const float* src = obs_x + (size_t)(b0 + row) * 256 + u * 8;
            float4 v0 = *(const float4*)src;
            float4 v1 = *(const float4*)(src + 4);
            pk = make_uint4(h2_u32(__floats2half2_rn(v0.x, v0.y)),
                            h2_u32(__floats2half2_rn(v0.z, v0.w)),
                            h2_u32(__floats2half2_rn(v1.x, v1.y)),
                            h2_u32(__floats2half2_rn(v1.z, v1.w)));
        }
        *(uint4*)(sm + OFF_A2 + row * 512 + up * 16) = pk;
    }

    // ---- warp tiling: 4 m-slabs (32 rows) x 4 n-quarters (32 cols per 128-col pass) ----
    const int wm = w & 3, wn = w >> 2;
    const int m0 = wm * 32;
    const int lrow = lane & 15, lkh = lane >> 4;
    const int arow0 = m0 + lrow, arow1 = m0 + 16 + lrow;
    const uint32_t a_base0 = sb + OFF_A + (uint32_t)arow0 * 512u;
    const uint32_t a_base1 = sb + OFF_A + (uint32_t)arow1 * 512u;
    const uint32_t a2_base = sb + OFF_A2 + (uint32_t)lrow * 512u;
    const int g = lane >> 2, c = lane & 3;
    const int n0 = wn * 32 + lrow, n1 = n0 + 16;

    uint32_t acc[2][2][4][2];   // [pass-in-half][mi][ni][2]
    uint32_t oacc[2][2];        // [pass-in-half][2]
    uint32_t af[4][2][4];       // [ks][mi][4], cached per kc
    uint32_t a2f[4][4];         // [ks][4],     cached per kc

    for (int half = 0; half < 2; half++) {
        #pragma unroll
        for (int pp = 0; pp < 2; pp++) {
            #pragma unroll
            for (int mi = 0; mi < 2; mi++)
                #pragma unroll
                for (int ni = 0; ni < 4; ni++) { acc[pp][mi][ni][0] = 0u; acc[pp][mi][ni][1] = 0u; }
            oacc[pp][0] = 0u; oacc[pp][1] = 0u;
        }

        for (int kc = 0; kc < 4; kc++) {
            #pragma unroll
            for (int pp = 0; pp < 2; pp++) {
                const int ci = half * 8 + kc * 2 + pp;
                if (ci == 15) asm volatile("cp.async.wait_group 0;" ::: "memory");
                else          asm volatile("cp.async.wait_group 1;" ::: "memory");
                __syncthreads();
                if (ci <= 13) load_chunk(sb, ci + 2, t);

                if (pp == 0) {  // A / A2 fragments for this kc, reused for both passes
                    #pragma unroll
                    for (int ks = 0; ks < 4; ks++) {
                        const int u = kc * 8 + ks * 2 + lkh;
                        ldsm4(af[ks][0], a_base0 + (uint32_t)(((u & 24) | ((u ^ arow0) & 7)) << 4));
                        ldsm4(af[ks][1], a_base1 + (uint32_t)(((u & 24) | ((u ^ arow1) & 7)) << 4));
                        ldsm4(a2f[ks],   a2_base + (uint32_t)(((u & 24) | ((u ^ lrow) & 7)) << 4));
                    }
                }

                const uint32_t bbuf = sb + OFF_B + (uint32_t)(ci % 3) * 16384u;
                #pragma unroll
                for (int ks = 0; ks < 4; ks++) {
                    uint32_t bf0[4], bf1[4];
                    ldsm4(bf0, bbuf + (uint32_t)n0 * 128u + (uint32_t)(((ks * 2 + lkh) ^ (n0 & 7)) << 4));
                    ldsm4(bf1, bbuf + (uint32_t)n1 * 128u + (uint32_t)(((ks * 2 + lkh) ^ (n1 & 7)) << 4));

                    mmah(acc[pp][0][0], af[ks][0], bf0);  mmah(acc[pp][0][1], af[ks][0], bf0 + 2);
                    mmah(acc[pp][0][2], af[ks][0], bf1);  mmah(acc[pp][0][3], af[ks][0], bf1 + 2);
                    mmah(acc[pp][1][0], af[ks][1], bf0);  mmah(acc[pp][1][1], af[ks][1], bf0 + 2);
                    mmah(acc[pp][1][2], af[ks][1], bf1);  mmah(acc[pp][1][3], af[ks][1], bf1 + 2);
                    const uint32_t* bt = (wm == 0) ? bf0 : (wm == 1) ? (bf0 + 2)
                                       : (wm == 2) ? bf1 : (bf1 + 2);
                    mmah(oacc[pp], a2f[ks], bt);
                }
            }
        }

        // ---- epilogue for this half's two passes ----
        if (half == 1) __syncthreads();  // B ring dies; Z block3 overlays buffers
        #pragma unroll
        for (int pp = 0; pp < 2; pp++) {
            const int pass = half * 2 + pp;
            #pragma unroll
            for (int mi = 0; mi < 2; mi++)
                #pragma unroll
                for (int ni = 0; ni < 4; ni++) {
                    const int ncol = pass * 128 + wn * 32 + ni * 8 + 2 * c;
                    const __half2 bias = *(__half2*)(sm + OFF_BS1 + ncol * 2);
                    const int p = ncol >> 1;
                    const int r0 = m0 + mi * 16 + g;
                    *(__half2*)(sm + zaddr(r0, p)) =
                        __hadd2(*(__half2*)&acc[pp][mi][ni][0], bias);
                    *(__half2*)(sm + zaddr(r0 + 8, p)) =
                        __hadd2(*(__half2*)&acc[pp][mi][ni][1], bias);
                }
            if (g < 2) {  // obs rows -> xsf (g = batch); warp covers n8 at wn*32+wm*8
                const int col = pass * 128 + wn * 32 + wm * 8 + 2 * c;
                const __half2 bias = *(__half2*)(sm + OFF_BS1 + col * 2);
                *(__half2*)(sm + OFF_XSF + (g * 512 + col) * 2) =
                    __hadd2(*(__half2*)&oacc[pp][0], bias);
            }
        }
    }
    __syncthreads();   // GEMM done; A region becomes scratch

    float* redp = (float*)(sm + SC_RED);
    float* betp = (float*)(sm + SC_BET);
    float* carr = (float*)(sm + SC_C);
    float* mscp = (float*)(sm + SC_MSC);

    // ---- alpha[n] = x . y[n] / sqrt(512) ----
    {
        int batch = t >> 8, tt = t & 255;
        int n = tt & 63, q = tt >> 6;
        int row = batch * 64 + n;
        const __half* xh = xsfh + batch * 512;
        float s = 0.f;
        #pragma unroll 8
        for (int pp = 0; pp < 64; pp++) {
            int p = q * 64 + pp;
            float2 yf = __half22float2(*(__half2*)(sm + zaddr(row, p)));
            float2 xf = __half22float2(*(const __half2*)(xh + 2 * p));
            s = fmaf(xf.x, yf.x, s);
            s = fmaf(xf.y, yf.y, s);
        }
        redp[t] = s;
    }
    __syncthreads();
    if (t < 128) {
        int batch = t >> 6, n = t & 63;
        const float* r = redp + batch * 256;
        betp[t] = (r[n] + r[64 + n] + r[128 + n] + r[192 + n]) * 0.04419417382415922f;
    }
    __syncthreads();
    if (w < 2) {  // softmax over 64
        float a0 = betp[w * 64 + lane], a1 = betp[w * 64 + 32 + lane];
        float m = fmaxf(a0, a1);
        #pragma unroll
        for (int off = 16; off; off >>= 1) m = fmaxf(m, __shfl_xor_sync(~0u, m, off));
        float e0 = __expf(a0 - m), e1 = __expf(a1 - m);
        float s = e0 + e1;
        #pragma unroll
        for (int off = 16; off; off >>= 1) s += __shfl_xor_sync(~0u, s, off);
        float inv = 1.0f / s;
        betp[w * 64 + lane] = e0 * inv;
        betp[w * 64 + 32 + lane] = e1 * inv;
    }
    __syncthreads();

    // ---- c[d] = sum_n beta[n] * y[n][d] ----
    {
        int batch = t >> 8, p = t & 255;
        float c0 = 0.f, c1 = 0.f;
        #pragma unroll 8
        for (int n = 0; n < 64; n++) {
            float be = betp[batch * 64 + n];
            float2 yf = __half22float2(*(__half2*)(sm + zaddr(batch * 64 + n, p)));
            c0 = fmaf(be, yf.x, c0);
            c1 = fmaf(be, yf.y, c1);
        }
        carr[batch * 512 + 2 * p]     = c0;
        carr[batch * 512 + 2 * p + 1] = c1;
    }
    __syncthreads();

    // ---- o2 = [x, c] @ W2 + b2: W2 read once, both batches ----
    {
        int q = t >> 6;      // k-chunk 0..7 of 128; q<4 -> x (f16), else c (f32)
        int jp = t & 63;
        const __half* w2p = g_W2h + (size_t)(q * 128) * 128 + jp * 2;
        float a00 = 0.f, a01 = 0.f, a10 = 0.f, a11 = 0.f;
        if (q < 4) {
            const __half* x0 = xsfh + q * 128;
            const __half* x1 = x0 + 512;
            #pragma unroll 8
            for (int k = 0; k < 128; k++) {
                float2 hf = __half22float2(*(const __half2*)(w2p + (size_t)k * 128));
                float v0 = __half2float(x0[k]), v1 = __half2float(x1[k]);
                a00 = fmaf(v0, hf.x, a00); a01 = fmaf(v0, hf.y, a01);
                a10 = fmaf(v1, hf.x, a10); a11 = fmaf(v1, hf.y, a11);
            }
        } else {
            const float* c0p = carr + (q - 4) * 128;
            const float* c1p = c0p + 512;
            #pragma unroll 8
            for (int k = 0; k < 128; k++) {
                float2 hf = __half22float2(*(const __half2*)(w2p + (size_t)k * 128));
                float v0 = c0p[k], v1 = c1p[k];
                a00 = fmaf(v0, hf.x, a00); a01 = fmaf(v0, hf.y, a01);
                a10 = fmaf(v1, hf.x, a10); a11 = fmaf(v1, hf.y, a11);
            }
        }
        float2* p2 = (float2*)(sm + SC_PART);
        p2[q * 64 + jp]       = make_float2(a00, a01);
        p2[512 + q * 64 + jp] = make_float2(a10, a11);
    }
    __syncthreads();

    // ---- combine + softmax over 128 + mask + write ----
    float sval = 0.f, eval = 0.f;
    int batch = 0, j = 0;
    if (t < 256) {
        batch = t >> 7; j = t & 127;
        const float2* p2 = (const float2*)(sm + SC_PART) + batch * 512 + (j >> 1);
        float s = 0.f;
        #pragma unroll
        for (int q = 0; q < 8; q++) {
            float2 v = p2[q * 64];
            s += (j & 1) ? v.y : v.x;
        }
        sval = s + __half2float(bs2h[j]);
        float m = sval;
        #pragma unroll
        for (int off = 16; off; off >>= 1) m = fmaxf(m, __shfl_xor_sync(~0u, m, off));
        if (lane == 0) mscp[w] = m;
    }
    __syncthreads();
    if (t < 256) {
        float m = fmaxf(fmaxf(mscp[batch * 4 + 0], mscp[batch * 4 + 1]),
                        fmaxf(mscp[batch * 4 + 2], mscp[batch * 4 + 3]));
        eval = __expf(sval - m);
        float ss = eval;
        #pragma unroll
        for (int off = 16; off; off >>= 1) ss += __shfl_xor_sync(~0u, ss, off);
        if (lane == 0) mscp[8 + w] = ss;
    }
    __syncthreads();
    if (t < 256) {
        float ssum = mscp[8 + batch * 4] + mscp[8 + batch * 4 + 1]
                   + mscp[8 + batch * 4 + 2] + mscp[8 + batch * 4 + 3];
        float soft = eval / ssum;
        float mv = (float)action_mask[(size_t)(b0 + batch) * 128 + j];
        out[(size_t)(b0 + batch) * 128 + j] = soft + NEGC * (1.0f - mv);
    }
}

extern "C" void kernel_launch(void* const* d_in, const int* in_sizes, int n_in,
                              void* d_out, int out_size)
{
    const float* obs_x       = (const float*)d_in[0];
    const float* others      = (const float*)d_in[1];
    const int*   action_mask = (const int*)  d_in[2];
    const float* W1          = (const float*)d_in[3];
    const float* b1          = (const float*)d_in[4];
    const float* W2          = (const float*)d_in[5];
    const float* b2          = (const float*)d_in[6];
    // d_in[7..10] = W3,b3,W4,b4: dead in reference forward(), unused.

    prep_kernel<<<256, 256>>>(W1, W2);

    cudaFuncSetAttribute(agent_main,
                         cudaFuncAttributeMaxDynamicSharedMemorySize, (int)SMEM_TOTAL);
    agent_main<<<2048, 512, SMEM_TOTAL>>>(obs_x, others, action_mask,
                                          b1, b2, (float*)d_out);
}

// round 9
// speedup vs baseline: 3.6104x; 3.4782x over previous
#include <cuda_runtime.h>
#include <cuda_fp16.h>
#include <cstdint>

#define NEGC (-10000000.0f)

// ---------------- device globals ----------------
__device__ __half g_W1T[512 * 256];    // W1T[n][k] = W1[k][n]
__device__ __half g_W1R[256 * 512];    // W1 row-major f16
__device__ __half g_W2T[128 * 1024];   // W2T[j][i] = W2[i][j]
__device__ __half g_X [4096 * 512];    // X = obs @ W1 + b1
__device__ __half g_V [4096 * 256];    // V = X @ W1^T  (v_b = W1 x_b)
__device__ __half g_Ab[4096 * 256];    // abar = beta^T A

// ---------------- helpers ----------------
__device__ __forceinline__ uint32_t smem_u32(const void* p) {
    uint32_t a;
    asm("{ .reg .u64 t; cvta.to.shared.u64 t, %1; cvt.u32.u64 %0, t; }" : "=r"(a) : "l"(p));
    return a;
}
__device__ __forceinline__ void ldsm4(uint32_t* r, uint32_t addr) {
    asm volatile("ldmatrix.sync.aligned.m8n8.x4.shared.b16 {%0,%1,%2,%3}, [%4];"
        : "=r"(r[0]), "=r"(r[1]), "=r"(r[2]), "=r"(r[3]) : "r"(addr));
}
__device__ __forceinline__ void mmah(uint32_t* d, const uint32_t* a, const uint32_t* b) {
    asm volatile("mma.sync.aligned.m16n8k16.row.col.f16.f16.f16.f16 "
        "{%0,%1}, {%2,%3,%4,%5}, {%6,%7}, {%0,%1};"
        : "+r"(d[0]), "+r"(d[1])
        : "r"(a[0]), "r"(a[1]), "r"(a[2]), "r"(a[3]), "r"(b[0]), "r"(b[1]));
}
__device__ __forceinline__ uint32_t sw_up(int u, int row) {
    return (uint32_t)((u & ~7) | ((u ^ row) & 7));
}
// load f16 tile (rows x U 16B-units per row) into swizzled smem
__device__ __forceinline__ void ld_tile(char* dst, const __half* src, int rows, int U,
                                        int srcStride, int t, int T) {
    int total = rows * U;
    for (int idx = t; idx < total; idx += T) {
        int row = idx / U, u = idx - row * U;
        uint4 v = *(const uint4*)(src + (size_t)row * srcStride + u * 8);
        *(uint4*)(dst + (size_t)row * U * 16 + sw_up(u, row) * 16) = v;
    }
}
__device__ __forceinline__ uint32_t h2u(__half2 h) { return *(uint32_t*)&h; }

// ---------------- prep ----------------
__global__ void prep_kernel(const float* __restrict__ W1, const float* __restrict__ W2) {
    int i = blockIdx.x * blockDim.x + threadIdx.x;
    int stride = gridDim.x * blockDim.x;
    for (int idx = i; idx < 512 * 256; idx += stride) {
        int n = idx >> 8, k = idx & 255;
        g_W1T[idx] = __float2half(W1[k * 512 + n]);
    }
    for (int idx = i; idx < 256 * 512; idx += stride)
        g_W1R[idx] = __float2half(W1[idx]);
    for (int idx = i; idx < 128 * 1024; idx += stride) {
        int j = idx >> 10, k = idx & 1023;
        g_W2T[idx] = __float2half(W2[k * 128 + j]);
    }
}

// ---------------- GEMM1: X[4096,512] = obs[4096,256] @ W1 + b1 ----------------
// grid 256: bm=bid&63 (64 rows), bn=bid>>6 (128 cols). smem: A 32K, B 64K, b1 256B.
__global__ __launch_bounds__(512, 2)
void gemm1(const float* __restrict__ obs, const float* __restrict__ b1g) {
    extern __shared__ char sm[];
    const uint32_t sb = smem_u32(sm);
    char* smA = sm;             // 64 x 32u
    char* smB = sm + 32768;     // 128 x 32u
    __half* b1s = (__half*)(sm + 98304);
    const int t = threadIdx.x, w = t >> 5, lane = t & 31;
    const int bm = blockIdx.x & 63, bn = blockIdx.x >> 6;

    // A: obs fp32 -> f16 swizzled
    #pragma unroll
    for (int it = 0; it < 4; it++) {
        int idx = it * 512 + t;
        int row = idx >> 5, u = idx & 31;
        const float* src = obs + (size_t)(bm * 64 + row) * 256 + u * 8;
        float4 v0 = *(const float4*)src, v1 = *(const float4*)(src + 4);
        uint4 pk = make_uint4(h2u(__floats2half2_rn(v0.x, v0.y)), h2u(__floats2half2_rn(v0.z, v0.w)),
                              h2u(__floats2half2_rn(v1.x, v1.y)), h2u(__floats2half2_rn(v1.z, v1.w)));
        *(uint4*)(smA + row * 512 + sw_up(u, row) * 16) = pk;
    }
    ld_tile(smB, g_W1T + (size_t)(bn * 128) * 256, 128, 32, 256, t, 512);
    if (t < 128) b1s[t] = __float2half(b1g[bn * 128 + t]);
    __syncthreads();

    const int wm = w & 3, wn = w >> 2;
    const int lrow = lane & 15, lkh = lane >> 4;
    const int mrow = wm * 16 + lrow;
    const int nb0 = wn * 32 + lrow, nb1 = nb0 + 16;
    const int g = lane >> 2, c = lane & 3;

    uint32_t acc[4][2] = {};
    #pragma unroll
    for (int ks = 0; ks < 16; ks++) {
        const int u = ks * 2 + lkh;
        uint32_t af[4], bf0[4], bf1[4];
        ldsm4(af,  sb + (uint32_t)(mrow * 512) + sw_up(u, mrow) * 16);
        ldsm4(bf0, sb + 32768u + (uint32_t)(nb0 * 512) + sw_up(u, nb0) * 16);
        ldsm4(bf1, sb + 32768u + (uint32_t)(nb1 * 512) + sw_up(u, nb1) * 16);
        mmah(acc[0], af, bf0); mmah(acc[1], af, bf0 + 2);
        mmah(acc[2], af, bf1); mmah(acc[3], af, bf1 + 2);
    }
    #pragma unroll
    for (int ni = 0; ni < 4; ni++) {
        const int ncol = wn * 32 + ni * 8 + 2 * c;
        const __half2 bias = *(__half2*)&b1s[ncol];
        const int r0 = wm * 16 + g;
        __half* dst = g_X + (size_t)(bm * 64 + r0) * 512 + bn * 128 + ncol;
        *(__half2*)dst            = __hadd2(*(__half2*)&acc[ni][0], bias);
        *(__half2*)(dst + 8*512)  = __hadd2(*(__half2*)&acc[ni][1], bias);
    }
}

// ---------------- GEMM2: V[4096,256] = X[4096,512] @ W1R^T ----------------
// grid 256: bm=bid&63 (64 rows), bn=bid>>6 (64 cols). smem: A 64K, B 64K.
__global__ __launch_bounds__(512, 1)
void gemm2() {
    extern __shared__ char sm[];
    const uint32_t sb = smem_u32(sm);
    const int t = threadIdx.x, w = t >> 5, lane = t & 31;
    const int bm = blockIdx.x & 63, bn = blockIdx.x >> 6;

    ld_tile(sm,          g_X   + (size_t)(bm * 64) * 512, 64, 64, 512, t, 512);
    ld_tile(sm + 65536,  g_W1R + (size_t)(bn * 64) * 512, 64, 64, 512, t, 512);
    __syncthreads();

    const int wm = w & 3, wn = w >> 2;
    const int lrow = lane & 15, lkh = lane >> 4;
    const int mrow = wm * 16 + lrow;
    const int nb = wn * 16 + lrow;
    const int g = lane >> 2, c = lane & 3;

    uint32_t acc[2][2] = {};
    #pragma unroll
    for (int ks = 0; ks < 32; ks++) {
        const int u = ks * 2 + lkh;
        uint32_t af[4], bf[4];
        ldsm4(af, sb + (uint32_t)(mrow * 1024) + sw_up(u, mrow) * 16);
        ldsm4(bf, sb + 65536u + (uint32_t)(nb * 1024) + sw_up(u, nb) * 16);
        mmah(acc[0], af, bf); mmah(acc[1], af, bf + 2);
    }
    #pragma unroll
    for (int ni = 0; ni < 2; ni++) {
        const int ncol = wn * 16 + ni * 8 + 2 * c;
        const int r0 = wm * 16 + g;
        __half* dst = g_V + (size_t)(bm * 64 + r0) * 256 + bn * 64 + ncol;
        *(__half2*)dst           = *(__half2*)&acc[ni][0];
        *(__half2*)(dst + 8*256) = *(__half2*)&acc[ni][1];
    }
}

// ---------------- K2: per-batch attention over others (streaming) ----------------
// grid 4096, 256 threads. alpha[n]=a_n.v (softmax shift-invariance kills x.b1 term)
__global__ __launch_bounds__(256, 3)
void attn_kernel(const float* __restrict__ others) {
    extern __shared__ char sm[];
    float* A   = (float*)sm;            // [64][256]
    float* v   = (float*)(sm + 65536);  // [256]
    float* alp = (float*)(sm + 66560);  // [64]
    const int t = threadIdx.x, w = t >> 5, lane = t & 31;
    const int b = blockIdx.x;

    const float4* src = (const float4*)(others + (size_t)b * 16384);
    #pragma unroll
    for (int i = 0; i < 16; i++)
        ((float4*)A)[i * 256 + t] = src[i * 256 + t];
    v[t] = __half2float(g_V[(size_t)b * 256 + t]);
    __syncthreads();

    // dots: warp w -> rows 8w..8w+7
    #pragma unroll
    for (int r = 0; r < 8; r++) {
        const int n = w * 8 + r;
        const float* ar = A + n * 256;
        float s = 0.f;
        #pragma unroll
        for (int i = 0; i < 8; i++) s = fmaf(ar[lane + 32 * i], v[lane + 32 * i], s);
        #pragma unroll
        for (int off = 16; off; off >>= 1) s += __shfl_xor_sync(~0u, s, off);
        if (lane == 0) alp[n] = s * 0.04419417382415922f;
    }
    __syncthreads();
    if (w == 0) {  // softmax over 64
        float a0 = alp[lane], a1 = alp[lane + 32];
        float m = fmaxf(a0, a1);
        #pragma unroll
        for (int off = 16; off; off >>= 1) m = fmaxf(m, __shfl_xor_sync(~0u, m, off));
        float e0 = __expf(a0 - m), e1 = __expf(a1 - m);
        float s = e0 + e1;
        #pragma unroll
        for (int off = 16; off; off >>= 1) s += __shfl_xor_sync(~0u, s, off);
        float inv = 1.0f / s;
        alp[lane] = e0 * inv; alp[lane + 32] = e1 * inv;
    }
    __syncthreads();
    float acc = 0.f;
    #pragma unroll 8
    for (int n = 0; n < 64; n++) acc = fmaf(alp[n], A[n * 256 + t], acc);
    g_Ab[(size_t)b * 256 + t] = __float2half(acc);
}

// ---------------- GEMM3: C = Abar@W1 + b1; logits=[X,C]@W2 + b2; softmax+mask ----------------
// grid 128: 32 batch rows each.
__global__ __launch_bounds__(512, 1)
void gemm3(const float* __restrict__ b1g, const float* __restrict__ b2g,
           const int* __restrict__ action_mask, float* __restrict__ out) {
    extern __shared__ char sm[];
    const uint32_t sb = smem_u32(sm);
    char* Xt = sm;              // 32 x 64u (32K)
    char* Ct = sm + 32768;      // 32 x 64u (32K)
    char* At = sm + 65536;      // 32 x 32u (16K)
    char* Bb = sm + 81920;      // 128 x 32u (64K)
    __half* b1s = (__half*)(sm + 147456);
    __half* b2s = (__half*)(sm + 148480);
    float*  ls  = (float*)(sm + 148736);   // [32][132]
    const int t = threadIdx.x, w = t >> 5, lane = t & 31;
    const int bm = blockIdx.x;

    ld_tile(Xt, g_X  + (size_t)(bm * 32) * 512, 32, 64, 512, t, 512);
    ld_tile(At, g_Ab + (size_t)(bm * 32) * 256, 32, 32, 256, t, 512);
    b1s[t & 511] = __float2half(b1g[t & 511]);
    if (t < 128) b2s[t] = __float2half(b2g[t]);

    const int wm = w & 1, wn = w >> 1;
    const int lrow = lane & 15, lkh = lane >> 4;
    const int mrow = wm * 16 + lrow;
    const int nb = wn * 16 + lrow;
    const int g = lane >> 2, c = lane & 3;

    // ---- phase 1: C = Abar @ W1 + b1, stored f16 swizzled into Ct ----
    for (int npass = 0; npass < 4; npass++) {
        __syncthreads();
        ld_tile(Bb, g_W1T + (size_t)(npass * 128) * 256, 128, 32, 256, t, 512);
        __syncthreads();
        uint32_t acc[2][2] = {};
        #pragma unroll
        for (int ks = 0; ks < 16; ks++) {
            const int u = ks * 2 + lkh;
            uint32_t af[4], bf[4];
            ldsm4(af, sb + 65536u + (uint32_t)(mrow * 512) + sw_up(u, mrow) * 16);
            ldsm4(bf, sb + 81920u + (uint32_t)(nb * 512) + sw_up(u, nb) * 16);
            mmah(acc[0], af, bf); mmah(acc[1], af, bf + 2);
        }
        #pragma unroll
        for (int ni = 0; ni < 2; ni++) {
            const int ncolG = npass * 128 + wn * 16 + ni * 8 + 2 * c;
            const __half2 bias = *(__half2*)&b1s[ncolG];
            const int u = ncolG >> 3, ob = (ncolG & 7) * 2;
            const int r0 = wm * 16 + g;
            *(__half2*)(Ct + r0 * 1024 + sw_up(u, r0) * 16 + ob) =
                __hadd2(*(__half2*)&acc[ni][0], bias);
            *(__half2*)(Ct + (r0 + 8) * 1024 + sw_up(u, r0 + 8) * 16 + ob) =
                __hadd2(*(__half2*)&acc[ni][1], bias);
        }
    }

    // ---- phase 2: logits[32][128] = [X,C] @ W2 (K=1024 in 4 chunks) ----
    uint32_t acc[2][2] = {};
    for (int kc = 0; kc < 4; kc++) {
        __syncthreads();
        ld_tile(Bb, g_W2T + kc * 256, 128, 32, 1024, t, 512);
        __syncthreads();
        const uint32_t abase = sb + ((kc < 2) ? 0u : 32768u);
        const int uoff = (kc & 1) * 32;
        #pragma unroll
        for (int ks = 0; ks < 16; ks++) {
            const int u = uoff + ks * 2 + lkh;
            const int u2 = ks * 2 + lkh;
            uint32_t af[4], bf[4];
            ldsm4(af, abase + (uint32_t)(mrow * 1024) + sw_up(u, mrow) * 16);
            ldsm4(bf, sb + 81920u + (uint32_t)(nb * 512) + sw_up(u2, nb) * 16);
            mmah(acc[0], af, bf); mmah(acc[1], af, bf + 2);
        }
    }
    #pragma unroll
    for (int ni = 0; ni < 2; ni++) {
        const int col = wn * 16 + ni * 8 + 2 * c;
        float2 b2v = __half22float2(*(__half2*)&b2s[col]);
        const int r0 = wm * 16 + g;
        float2 v0 = __half22float2(*(__half2*)&acc[ni][0]);
        float2 v1 = __half22float2(*(__half2*)&acc[ni][1]);
        ls[r0 * 132 + col]           = v0.x + b2v.x;
        ls[r0 * 132 + col + 1]       = v0.y + b2v.y;
        ls[(r0 + 8) * 132 + col]     = v1.x + b2v.x;
        ls[(r0 + 8) * 132 + col + 1] = v1.y + b2v.y;
    }
    __syncthreads();

    // ---- softmax(128) + mask + write: warp w handles rows 2w, 2w+1 ----
    #pragma unroll
    for (int rr = 0; rr < 2; rr++) {
        const int row = w * 2 + rr;
        float v0 = ls[row * 132 + lane],      v1 = ls[row * 132 + lane + 32];
        float v2 = ls[row * 132 + lane + 64], v3 = ls[row * 132 + lane + 96];
        float m = fmaxf(fmaxf(v0, v1), fmaxf(v2, v3));
        #pragma unroll
        for (int off = 16; off; off >>= 1) m = fmaxf(m, __shfl_xor_sync(~0u, m, off));
        float e0 = __expf(v0 - m), e1 = __expf(v1 - m);
        float e2 = __expf(v2 - m), e3 = __expf(v3 - m);
        float s = e0 + e1 + e2 + e3;
        #pragma unroll
        for (int off = 16; off; off >>= 1) s += __shfl_xor_sync(~0u, s, off);
        const float inv = 1.0f / s;
        const size_t gb = (size_t)(bm * 32 + row);
        const int* mk = action_mask + gb * 128;
        float* op = out + gb * 128;
        op[lane]      = e0 * inv + NEGC * (1.0f - (float)mk[lane]);
        op[lane + 32] = e1 * inv + NEGC * (1.0f - (float)mk[lane + 32]);
        op[lane + 64] = e2 * inv + NEGC * (1.0f - (float)mk[lane + 64]);
        op[lane + 96] = e3 * inv + NEGC * (1.0f - (float)mk[lane + 96]);
    }
}

extern "C" void kernel_launch(void* const* d_in, const int* in_sizes, int n_in,
                              void* d_out, int out_size)
{
    const float* obs_x       = (const float*)d_in[0];
    const float* others      = (const float*)d_in[1];
    const int*   action_mask = (const int*)  d_in[2];
    const float* W1          = (const float*)d_in[3];
    const float* b1          = (const float*)d_in[4];
    const float* W2          = (const float*)d_in[5];
    const float* b2          = (const float*)d_in[6];
    // d_in[7..10] = W3,b3,W4,b4: dead in reference forward(), unused.

    static bool attr_done = false;
    if (!attr_done) {
        cudaFuncSetAttribute(gemm1, cudaFuncAttributeMaxDynamicSharedMemorySize, 98816);
        cudaFuncSetAttribute(gemm2, cudaFuncAttributeMaxDynamicSharedMemorySize, 131072);
        cudaFuncSetAttribute(attn_kernel, cudaFuncAttributeMaxDynamicSharedMemorySize, 66816);
        cudaFuncSetAttribute(gemm3, cudaFuncAttributeMaxDynamicSharedMemorySize, 165632);
        attr_done = true;
    }

    prep_kernel<<<256, 256>>>(W1, W2);
    gemm1<<<256, 512, 98816>>>(obs_x, b1);
    gemm2<<<256, 512, 131072>>>();
    attn_kernel<<<4096, 256, 66816>>>(others);
    gemm3<<<128, 512, 165632>>>(b1, b2, action_mask, (float*)d_out);
}